// round 5
// baseline (speedup 1.0000x reference)
#include <cuda_runtime.h>
#include <cuda_bf16.h>

// Problem constants (fixed by setup_inputs)
#define C_DIM   192
#define NHEADS  6
#define HDIM    32
#define WS2     64          // 8x8 window
#define NWIN    4096        // 4 * 32 * 32
#define MTOK    262144      // 4 * 256 * 256
#define QKV_N   576         // 3 * 192
#define SCALE_Q 0.17677669529663687f   // 32^-0.5

// Scratch (device globals: allocation-free per harness rules)
__device__ float g_q [NWIN * NHEADS * WS2 * HDIM];   // [win][head][pos][d]
__device__ float g_k [NWIN * NHEADS * WS2 * HDIM];
__device__ float g_v [NWIN * NHEADS * WS2 * HDIM];
__device__ float g_ao[MTOK * C_DIM];                 // [win*64+pos][C]

// ---------------------------------------------------------------------------
// GEMM core: 128(M) x 64(N) tile, BK=8, 128 threads, 8x8 per thread,
// double-buffered smem + register prefetch.
//   A: [M][192] row-major.  B: [N][192] row-major.  y = A * B^T.
// Per thread per k-step: 4 LDS.128 = 64B feeding 64 FMA.
// ---------------------------------------------------------------------------
__device__ __forceinline__ void gemm_core_128x64(
    const float* __restrict__ A, const float* __restrict__ Wm,
    int rowBase, int colBase,
    float (*As)[8][128], float (*Bs)[8][64],
    float (&acc)[8][8], int tid, int tx, int ty)
{
    const float* Aptr = A + (size_t)(rowBase + tid) * C_DIM;
    const int bRow = tid >> 1;
    const int bKg  = (tid & 1) * 4;
    const float* Bptr = Wm + (size_t)(colBase + bRow) * C_DIM + bKg;

#pragma unroll
    for (int i = 0; i < 8; i++)
#pragma unroll
        for (int j = 0; j < 8; j++) acc[i][j] = 0.f;

    // prefetch + store k-tile 0
    float4 a0 = *(const float4*)(Aptr + 0);
    float4 a1 = *(const float4*)(Aptr + 4);
    float4 b0 = *(const float4*)(Bptr + 0);
    As[0][0][tid] = a0.x; As[0][1][tid] = a0.y;
    As[0][2][tid] = a0.z; As[0][3][tid] = a0.w;
    As[0][4][tid] = a1.x; As[0][5][tid] = a1.y;
    As[0][6][tid] = a1.z; As[0][7][tid] = a1.w;
    Bs[0][bKg + 0][bRow] = b0.x; Bs[0][bKg + 1][bRow] = b0.y;
    Bs[0][bKg + 2][bRow] = b0.z; Bs[0][bKg + 3][bRow] = b0.w;
    __syncthreads();

    int buf = 0;
    for (int kt = 1; kt <= C_DIM / 8; kt++) {
        const int k0 = kt * 8;
        const bool more = (k0 < C_DIM);
        if (more) {
            a0 = *(const float4*)(Aptr + k0);
            a1 = *(const float4*)(Aptr + k0 + 4);
            b0 = *(const float4*)(Bptr + k0);
        }

#pragma unroll
        for (int kk = 0; kk < 8; kk++) {
            float4 x0 = *(const float4*)&As[buf][kk][ty * 8];
            float4 x1 = *(const float4*)&As[buf][kk][ty * 8 + 4];
            float4 y0 = *(const float4*)&Bs[buf][kk][tx * 8];
            float4 y1 = *(const float4*)&Bs[buf][kk][tx * 8 + 4];
            float av[8] = {x0.x, x0.y, x0.z, x0.w, x1.x, x1.y, x1.z, x1.w};
            float bb[8] = {y0.x, y0.y, y0.z, y0.w, y1.x, y1.y, y1.z, y1.w};
#pragma unroll
            for (int i = 0; i < 8; i++)
#pragma unroll
                for (int j = 0; j < 8; j++)
                    acc[i][j] = fmaf(av[i], bb[j], acc[i][j]);
        }

        if (more) {
            const int nb = buf ^ 1;
            As[nb][0][tid] = a0.x; As[nb][1][tid] = a0.y;
            As[nb][2][tid] = a0.z; As[nb][3][tid] = a0.w;
            As[nb][4][tid] = a1.x; As[nb][5][tid] = a1.y;
            As[nb][6][tid] = a1.z; As[nb][7][tid] = a1.w;
            Bs[nb][bKg + 0][bRow] = b0.x; Bs[nb][bKg + 1][bRow] = b0.y;
            Bs[nb][bKg + 2][bRow] = b0.z; Bs[nb][bKg + 3][bRow] = b0.w;
            __syncthreads();
            buf = nb;
        }
    }
}

// ---------------------------------------------------------------------------
// Kernel 1: QKV projection; epilogue scatters into window layout, scales q.
// ---------------------------------------------------------------------------
__global__ __launch_bounds__(128) void qkv_kernel(const float* __restrict__ X,
                                                  const float* __restrict__ Wm)
{
    __shared__ float As[2][8][128];
    __shared__ float Bs[2][8][64];
    const int tid = threadIdx.x;
    const int tx = tid & 7;
    const int ty = tid >> 3;
    const int rowBase = blockIdx.y << 7;
    const int colBase = blockIdx.x << 6;

    float acc[8][8];
    gemm_core_128x64(X, Wm, rowBase, colBase, As, Bs, acc, tid, tx, ty);

    // Epilogue: 8 consecutive n per thread = within one head (8 | 32 alignment)
    const int part = colBase / C_DIM;                 // 0=q,1=k,2=v
    const int crem = (colBase % C_DIM) + tx * 8;      // 0..184, multiple of 8
    const int head = crem >> 5;
    const int d0   = crem & 31;
    float* dst = (part == 0) ? g_q : (part == 1) ? g_k : g_v;
    const float mult = (part == 0) ? SCALE_Q : 1.f;

#pragma unroll
    for (int i = 0; i < 8; i++) {
        int m  = rowBase + ty * 8 + i;
        int b  = m >> 16;
        int hw = m & 65535;
        int h  = hw >> 8;
        int w  = hw & 255;
        int win = ((((b << 5) | (h >> 3)) << 5) | (w >> 3));
        int pos = ((h & 7) << 3) | (w & 7);
        size_t idx = (size_t)(win * NHEADS + head) * (WS2 * HDIM) + pos * HDIM + d0;
        float4 o0, o1;
        o0.x = acc[i][0] * mult; o0.y = acc[i][1] * mult;
        o0.z = acc[i][2] * mult; o0.w = acc[i][3] * mult;
        o1.x = acc[i][4] * mult; o1.y = acc[i][5] * mult;
        o1.z = acc[i][6] * mult; o1.w = acc[i][7] * mult;
        *(float4*)&dst[idx]     = o0;
        *(float4*)&dst[idx + 4] = o1;
    }
}

// ---------------------------------------------------------------------------
// Kernel 2: per-(window, head) attention. 64 threads, 1 query row per thread.
// ---------------------------------------------------------------------------
__global__ __launch_bounds__(64) void attn_kernel(const float* __restrict__ rpb)
{
    __shared__ float k_s[64][32];
    __shared__ float v_s[64][32];
    __shared__ float p_s[64][65];     // +1 pad: conflict-free rows
    __shared__ float bias_s[232];     // 225 used

    const int win  = blockIdx.x;
    const int head = blockIdx.y;
    const int tid  = threadIdx.x;

    const size_t base = (size_t)(win * NHEADS + head) * (WS2 * HDIM);

    const float4* kg4 = (const float4*)(g_k + base);
    const float4* vg4 = (const float4*)(g_v + base);
    float4* ks4 = (float4*)&k_s[0][0];
    float4* vs4 = (float4*)&v_s[0][0];
#pragma unroll
    for (int i = 0; i < 8; i++) {
        ks4[i * 64 + tid] = kg4[i * 64 + tid];
        vs4[i * 64 + tid] = vg4[i * 64 + tid];
    }
    for (int i = tid; i < 225; i += 64) bias_s[i] = rpb[i * NHEADS + head];

    float q[32];
    const float4* qg4 = (const float4*)(g_q + base + tid * HDIM);
#pragma unroll
    for (int i = 0; i < 8; i++) {
        float4 t = qg4[i];
        q[i * 4 + 0] = t.x; q[i * 4 + 1] = t.y;
        q[i * 4 + 2] = t.z; q[i * 4 + 3] = t.w;
    }
    __syncthreads();

    const int qy = tid >> 3, qx = tid & 7;

    float maxv = -1e30f;
#pragma unroll 4
    for (int j = 0; j < 64; j++) {
        float dot = 0.f;
#pragma unroll
        for (int d = 0; d < 32; d++) dot = fmaf(q[d], k_s[j][d], dot);
        int dy = qy - (j >> 3) + 7;
        int dx = qx - (j & 7) + 7;
        float s = dot + bias_s[dy * 15 + dx];
        p_s[tid][j] = s;
        maxv = fmaxf(maxv, s);
    }

    float sum = 0.f;
#pragma unroll
    for (int j = 0; j < 64; j++) {
        float e = __expf(p_s[tid][j] - maxv);
        p_s[tid][j] = e;
        sum += e;
    }
    const float inv = 1.f / sum;

    float acc[32];
#pragma unroll
    for (int d = 0; d < 32; d++) acc[d] = 0.f;
#pragma unroll 4
    for (int j = 0; j < 64; j++) {
        float p = p_s[tid][j];
#pragma unroll
        for (int d = 0; d < 32; d++) acc[d] = fmaf(p, v_s[j][d], acc[d]);
    }

    float* dst = g_ao + ((size_t)win * WS2 + tid) * C_DIM + head * HDIM;
#pragma unroll
    for (int i = 0; i < 8; i++) {
        float4 o;
        o.x = acc[i * 4 + 0] * inv;
        o.y = acc[i * 4 + 1] * inv;
        o.z = acc[i * 4 + 2] * inv;
        o.w = acc[i * 4 + 3] * inv;
        *(float4*)&dst[i * 4] = o;
    }
}

// ---------------------------------------------------------------------------
// Kernel 3: output projection + bias, un-windowing scatter epilogue.
// ---------------------------------------------------------------------------
__global__ __launch_bounds__(128) void proj_kernel(const float* __restrict__ Wm,
                                                   const float* __restrict__ bias,
                                                   float* __restrict__ out)
{
    __shared__ float As[2][8][128];
    __shared__ float Bs[2][8][64];
    const int tid = threadIdx.x;
    const int tx = tid & 7;
    const int ty = tid >> 3;
    const int rowBase = blockIdx.y << 7;
    const int colBase = blockIdx.x << 6;

    float acc[8][8];
    gemm_core_128x64(g_ao, Wm, rowBase, colBase, As, Bs, acc, tid, tx, ty);

    const int n0 = colBase + tx * 8;
    const float4 bv0 = *(const float4*)&bias[n0];
    const float4 bv1 = *(const float4*)&bias[n0 + 4];

#pragma unroll
    for (int i = 0; i < 8; i++) {
        int mp  = rowBase + ty * 8 + i;        // window-ordered token id
        int win = mp >> 6;
        int pos = mp & 63;
        int b   = win >> 10;
        int wr  = win & 1023;
        int wh  = wr >> 5;
        int ww  = wr & 31;
        int h   = (wh << 3) | (pos >> 3);
        int w   = (ww << 3) | (pos & 7);
        size_t oidx = ((size_t)((b << 16) | (h << 8) | w)) * C_DIM + n0;
        float4 o0, o1;
        o0.x = acc[i][0] + bv0.x; o0.y = acc[i][1] + bv0.y;
        o0.z = acc[i][2] + bv0.z; o0.w = acc[i][3] + bv0.w;
        o1.x = acc[i][4] + bv1.x; o1.y = acc[i][5] + bv1.y;
        o1.z = acc[i][6] + bv1.z; o1.w = acc[i][7] + bv1.w;
        *(float4*)&out[oidx]     = o0;
        *(float4*)&out[oidx + 4] = o1;
    }
}

// ---------------------------------------------------------------------------
extern "C" void kernel_launch(void* const* d_in, const int* in_sizes, int n_in,
                              void* d_out, int out_size)
{
    const float* x      = (const float*)d_in[0];
    const float* qkv_w  = (const float*)d_in[1];
    const float* proj_w = (const float*)d_in[2];
    const float* proj_b = (const float*)d_in[3];
    const float* rpb    = (const float*)d_in[4];
    float* out = (float*)d_out;

    // QKV: M=262144 (2048 tiles of 128), N=576 (9 tiles of 64)
    qkv_kernel<<<dim3(QKV_N / 64, MTOK / 128), 128>>>(x, qkv_w);

    // Attention: one block per (window, head)
    attn_kernel<<<dim3(NWIN, NHEADS), 64>>>(rpb);

    // Projection: N=192 (3 tiles of 64)
    proj_kernel<<<dim3(C_DIM / 64, MTOK / 128), 128>>>(proj_w, proj_b, out);
}

// round 8
// speedup vs baseline: 1.1025x; 1.1025x over previous
#include <cuda_runtime.h>
#include <cuda_bf16.h>
#include <cstdint>

// Problem constants (fixed by setup_inputs)
#define C_DIM   192
#define NHEADS  6
#define HDIM    32
#define WS2     64
#define NWIN    4096
#define MTOK    262144
#define SCALE_Q 0.17677669529663687f

// Scratch (device globals: allocation-free per harness rules)
__device__ float g_q [NWIN * NHEADS * WS2 * HDIM];
__device__ float g_k [NWIN * NHEADS * WS2 * HDIM];
__device__ float g_v [NWIN * NHEADS * WS2 * HDIM];
__device__ float g_ao[MTOK * C_DIM];

// ---------------------------------------------------------------------------
// smem layout for the mma.sync GEMM (dynamic): bf16 tiles, K-chunk = 96,
// row stride 104 elements (52 words; 52 mod 32 = 20 -> conflict-free frags).
//   A  : 128 rows x 104  -> 26624 B each (hi, lo)
//   B  : 192 rows x 104  -> 39936 B each (hi, lo)
// ---------------------------------------------------------------------------
#define OFF_AHI 0
#define OFF_ALO 26624
#define OFF_BHI 53248
#define OFF_BLO 93184
#define SMEM_GEMM 133120
#define RSTRIDE 52            // 32-bit words per row

#define MMA16816(c, a, b0, b1)                                                   \
    asm volatile("mma.sync.aligned.m16n8k16.row.col.f32.bf16.bf16.f32 "          \
                 "{%0,%1,%2,%3}, {%4,%5,%6,%7}, {%8,%9}, {%0,%1,%2,%3};"         \
                 : "+f"((c)[0]), "+f"((c)[1]), "+f"((c)[2]), "+f"((c)[3])        \
                 : "r"((a)[0]), "r"((a)[1]), "r"((a)[2]), "r"((a)[3]),           \
                   "r"(b0), "r"(b1))

__device__ __forceinline__ void split4(float4 v, uint2& hi, uint2& lo) {
    float f[4] = {v.x, v.y, v.z, v.w};
    uint32_t hb[4], lb[4];
#pragma unroll
    for (int i = 0; i < 4; i++) {
        __nv_bfloat16 h = __float2bfloat16_rn(f[i]);
        __nv_bfloat16 l = __float2bfloat16_rn(f[i] - __bfloat162float(h));
        hb[i] = (uint32_t)__bfloat16_as_ushort(h);
        lb[i] = (uint32_t)__bfloat16_as_ushort(l);
    }
    hi = make_uint2(hb[0] | (hb[1] << 16), hb[2] | (hb[3] << 16));
    lo = make_uint2(lb[0] | (lb[1] << 16), lb[2] | (lb[3] << 16));
}

// Fill one K-chunk (96 cols) of A (128 rows) and B (192 rows) as split bf16.
__device__ __forceinline__ void fill_chunk(const float* __restrict__ Asrc,
                                           const float* __restrict__ Bsrc,
                                           char* sm, int kb, int tid)
{
    for (int i = tid; i < 128 * 24; i += 256) {
        int r = i / 24, c4 = i % 24, kl = c4 * 4;
        float4 v = *(const float4*)(Asrc + (size_t)r * C_DIM + kb + kl);
        uint2 hi, lo; split4(v, hi, lo);
        ((uint2*)(sm + OFF_AHI))[r * 26 + c4] = hi;
        ((uint2*)(sm + OFF_ALO))[r * 26 + c4] = lo;
    }
    for (int i = tid; i < 192 * 24; i += 256) {
        int n = i / 24, c4 = i % 24, kl = c4 * 4;
        float4 v = *(const float4*)(Bsrc + (size_t)n * C_DIM + kb + kl);
        uint2 hi, lo; split4(v, hi, lo);
        ((uint2*)(sm + OFF_BHI))[n * 26 + c4] = hi;
        ((uint2*)(sm + OFF_BLO))[n * 26 + c4] = lo;
    }
}

// Core accumulate: acc[4][6][4], warp tile 64(M) x 48(N) of the 128x192 block.
__device__ __forceinline__ void gemm_chunk(const char* sm, float (&acc)[4][6][4],
                                           int wid, int lane)
{
    const uint32_t* AHw = (const uint32_t*)(sm + OFF_AHI);
    const uint32_t* ALw = (const uint32_t*)(sm + OFF_ALO);
    const uint32_t* BHw = (const uint32_t*)(sm + OFF_BHI);
    const uint32_t* BLw = (const uint32_t*)(sm + OFF_BLO);
    const int mr = (wid >> 2) * 64 + (lane >> 2);
    const int nr = (wid & 3) * 48 + (lane >> 2);

#pragma unroll
    for (int ks = 0; ks < 6; ks++) {
        const int kw = ks * 8 + (lane & 3);
        uint32_t aH[4][4], aL[4][4];
#pragma unroll
        for (int mf = 0; mf < 4; mf++) {
            const int r0 = mr + mf * 16;
            aH[mf][0] = AHw[r0 * RSTRIDE + kw];
            aH[mf][1] = AHw[(r0 + 8) * RSTRIDE + kw];
            aH[mf][2] = AHw[r0 * RSTRIDE + kw + 4];
            aH[mf][3] = AHw[(r0 + 8) * RSTRIDE + kw + 4];
            aL[mf][0] = ALw[r0 * RSTRIDE + kw];
            aL[mf][1] = ALw[(r0 + 8) * RSTRIDE + kw];
            aL[mf][2] = ALw[r0 * RSTRIDE + kw + 4];
            aL[mf][3] = ALw[(r0 + 8) * RSTRIDE + kw + 4];
        }
#pragma unroll
        for (int nf = 0; nf < 6; nf++) {
            const int n0 = nr + nf * 8;
            uint32_t bh0 = BHw[n0 * RSTRIDE + kw];
            uint32_t bh1 = BHw[n0 * RSTRIDE + kw + 4];
            uint32_t bl0 = BLw[n0 * RSTRIDE + kw];
            uint32_t bl1 = BLw[n0 * RSTRIDE + kw + 4];
#pragma unroll
            for (int mf = 0; mf < 4; mf++) {
                MMA16816(acc[mf][nf], aH[mf], bh0, bh1);
                MMA16816(acc[mf][nf], aH[mf], bl0, bl1);
                MMA16816(acc[mf][nf], aL[mf], bh0, bh1);
            }
        }
    }
}

// ---------------------------------------------------------------------------
// Kernel 1: QKV projection (tensor core), window-layout scatter epilogue.
// grid: (MTOK/128, 3). blockIdx.y selects 192 output cols (q | k | v).
// ---------------------------------------------------------------------------
__global__ __launch_bounds__(256) void qkv_tc(const float* __restrict__ X,
                                              const float* __restrict__ Wq)
{
    extern __shared__ char sm[];
    const int tid = threadIdx.x, wid = tid >> 5, lane = tid & 31;
    const int rowBase = blockIdx.x << 7;
    const int part = blockIdx.y;

    float acc[4][6][4];
#pragma unroll
    for (int a = 0; a < 4; a++)
#pragma unroll
        for (int b = 0; b < 6; b++)
#pragma unroll
            for (int c = 0; c < 4; c++) acc[a][b][c] = 0.f;

    const float* Asrc = X + (size_t)rowBase * C_DIM;
    const float* Bsrc = Wq + (size_t)part * C_DIM * C_DIM;

    fill_chunk(Asrc, Bsrc, sm, 0, tid);
    __syncthreads();
    gemm_chunk(sm, acc, wid, lane);
    __syncthreads();
    fill_chunk(Asrc, Bsrc, sm, 96, tid);
    __syncthreads();
    gemm_chunk(sm, acc, wid, lane);

    float* dstArr = (part == 0) ? g_q : (part == 1) ? g_k : g_v;
    const float mult = (part == 0) ? SCALE_Q : 1.f;

#pragma unroll
    for (int mf = 0; mf < 4; mf++) {
#pragma unroll
        for (int rr = 0; rr < 2; rr++) {
            const int m = rowBase + (wid >> 2) * 64 + mf * 16 + (lane >> 2) + rr * 8;
            const int b  = m >> 16, h = (m >> 8) & 255, w = m & 255;
            const int win = ((((b << 5) | (h >> 3)) << 5) | (w >> 3));
            const int pos = ((h & 7) << 3) | (w & 7);
            float* rowp = dstArr + ((size_t)(win * NHEADS) << 11) + (pos << 5);
#pragma unroll
            for (int nf = 0; nf < 6; nf++) {
                const int n192 = (wid & 3) * 48 + nf * 8 + (lane & 3) * 2;
                const int head = n192 >> 5, d = n192 & 31;
                float2 o;
                o.x = acc[mf][nf][rr * 2 + 0] * mult;
                o.y = acc[mf][nf][rr * 2 + 1] * mult;
                *(float2*)(rowp + ((size_t)head << 11) + d) = o;
            }
        }
    }
}

// ---------------------------------------------------------------------------
// Kernel 3: output projection (tensor core) + bias, un-window epilogue.
// grid: (MTOK/128, 1).
// ---------------------------------------------------------------------------
__global__ __launch_bounds__(256) void proj_tc(const float* __restrict__ Wp,
                                               const float* __restrict__ bias,
                                               float* __restrict__ out)
{
    extern __shared__ char sm[];
    const int tid = threadIdx.x, wid = tid >> 5, lane = tid & 31;
    const int rowBase = blockIdx.x << 7;

    float acc[4][6][4];
#pragma unroll
    for (int a = 0; a < 4; a++)
#pragma unroll
        for (int b = 0; b < 6; b++)
#pragma unroll
            for (int c = 0; c < 4; c++) acc[a][b][c] = 0.f;

    const float* Asrc = g_ao + (size_t)rowBase * C_DIM;

    fill_chunk(Asrc, Wp, sm, 0, tid);
    __syncthreads();
    gemm_chunk(sm, acc, wid, lane);
    __syncthreads();
    fill_chunk(Asrc, Wp, sm, 96, tid);
    __syncthreads();
    gemm_chunk(sm, acc, wid, lane);

    // bias values for this thread's 6 column pairs
    float2 bv[6];
#pragma unroll
    for (int nf = 0; nf < 6; nf++) {
        const int n192 = (wid & 3) * 48 + nf * 8 + (lane & 3) * 2;
        bv[nf] = *(const float2*)(bias + n192);
    }

#pragma unroll
    for (int mf = 0; mf < 4; mf++) {
#pragma unroll
        for (int rr = 0; rr < 2; rr++) {
            const int m = rowBase + (wid >> 2) * 64 + mf * 16 + (lane >> 2) + rr * 8;
            const int win = m >> 6, pos = m & 63;
            const int bb = win >> 10, wr = win & 1023;
            const int hh = ((wr >> 5) << 3) | (pos >> 3);
            const int ww = ((wr & 31) << 3) | (pos & 7);
            float* obase = out + (size_t)((bb << 16) | (hh << 8) | ww) * C_DIM;
#pragma unroll
            for (int nf = 0; nf < 6; nf++) {
                const int n192 = (wid & 3) * 48 + nf * 8 + (lane & 3) * 2;
                float2 o;
                o.x = acc[mf][nf][rr * 2 + 0] + bv[nf].x;
                o.y = acc[mf][nf][rr * 2 + 1] + bv[nf].y;
                *(float2*)(obase + n192) = o;
            }
        }
    }
}

// ---------------------------------------------------------------------------
// Kernel 2: per-(window, head) attention (unchanged fp32 — verified in R2).
// ---------------------------------------------------------------------------
__global__ __launch_bounds__(64) void attn_kernel(const float* __restrict__ rpb)
{
    __shared__ float k_s[64][32];
    __shared__ float v_s[64][32];
    __shared__ float p_s[64][65];
    __shared__ float bias_s[232];

    const int win  = blockIdx.x;
    const int head = blockIdx.y;
    const int tid  = threadIdx.x;
    const size_t base = (size_t)(win * NHEADS + head) * (WS2 * HDIM);

    const float4* kg4 = (const float4*)(g_k + base);
    const float4* vg4 = (const float4*)(g_v + base);
    float4* ks4 = (float4*)&k_s[0][0];
    float4* vs4 = (float4*)&v_s[0][0];
#pragma unroll
    for (int i = 0; i < 8; i++) {
        ks4[i * 64 + tid] = kg4[i * 64 + tid];
        vs4[i * 64 + tid] = vg4[i * 64 + tid];
    }
    for (int i = tid; i < 225; i += 64) bias_s[i] = rpb[i * NHEADS + head];

    float q[32];
    const float4* qg4 = (const float4*)(g_q + base + tid * HDIM);
#pragma unroll
    for (int i = 0; i < 8; i++) {
        float4 t = qg4[i];
        q[i * 4 + 0] = t.x; q[i * 4 + 1] = t.y;
        q[i * 4 + 2] = t.z; q[i * 4 + 3] = t.w;
    }
    __syncthreads();

    const int qy = tid >> 3, qx = tid & 7;
    float maxv = -1e30f;
#pragma unroll 4
    for (int j = 0; j < 64; j++) {
        float dot = 0.f;
#pragma unroll
        for (int d = 0; d < 32; d++) dot = fmaf(q[d], k_s[j][d], dot);
        int dy = qy - (j >> 3) + 7;
        int dx = qx - (j & 7) + 7;
        float s = dot + bias_s[dy * 15 + dx];
        p_s[tid][j] = s;
        maxv = fmaxf(maxv, s);
    }

    float sum = 0.f;
#pragma unroll
    for (int j = 0; j < 64; j++) {
        float e = __expf(p_s[tid][j] - maxv);
        p_s[tid][j] = e;
        sum += e;
    }
    const float inv = 1.f / sum;

    float acc[32];
#pragma unroll
    for (int d = 0; d < 32; d++) acc[d] = 0.f;
#pragma unroll 4
    for (int j = 0; j < 64; j++) {
        float p = p_s[tid][j];
#pragma unroll
        for (int d = 0; d < 32; d++) acc[d] = fmaf(p, v_s[j][d], acc[d]);
    }

    float* dst = g_ao + ((size_t)win * WS2 + tid) * C_DIM + head * HDIM;
#pragma unroll
    for (int i = 0; i < 8; i++) {
        float4 o;
        o.x = acc[i * 4 + 0] * inv;
        o.y = acc[i * 4 + 1] * inv;
        o.z = acc[i * 4 + 2] * inv;
        o.w = acc[i * 4 + 3] * inv;
        *(float4*)&dst[i * 4] = o;
    }
}

// ---------------------------------------------------------------------------
extern "C" void kernel_launch(void* const* d_in, const int* in_sizes, int n_in,
                              void* d_out, int out_size)
{
    const float* x      = (const float*)d_in[0];
    const float* qkv_w  = (const float*)d_in[1];
    const float* proj_w = (const float*)d_in[2];
    const float* proj_b = (const float*)d_in[3];
    const float* rpb    = (const float*)d_in[4];
    float* out = (float*)d_out;

    cudaFuncSetAttribute(qkv_tc,  cudaFuncAttributeMaxDynamicSharedMemorySize, SMEM_GEMM);
    cudaFuncSetAttribute(proj_tc, cudaFuncAttributeMaxDynamicSharedMemorySize, SMEM_GEMM);

    qkv_tc<<<dim3(MTOK / 128, 3), 256, SMEM_GEMM>>>(x, qkv_w);
    attn_kernel<<<dim3(NWIN, NHEADS), 64>>>(rpb);
    proj_tc<<<dim3(MTOK / 128, 1), 256, SMEM_GEMM>>>(proj_w, proj_b, out);
}